// round 2
// baseline (speedup 1.0000x reference)
#include <cuda_runtime.h>
#include <math.h>
#include <stdint.h>

// Problem constants
#define NPOLY 2048      // B*N = 16*128
#define PP    64        // points per polygon
#define DD    128       // feature dim
#define NLAYER 3
#define LROWS 132       // padded SMEM row stride (floats); 132%32=4 -> conflict-free
#define LN_EPS 1e-5f

#define SMEM_FLOATS (2*PP*LROWS + 128 + 128 + 64)
#define SMEM_BYTES  (SMEM_FLOATS * 4)

typedef unsigned long long ull;

// 0 = mask buffer is int32 per element, 1 = mask buffer is 1 byte per element
__device__ int g_mask_is_byte;

__global__ void detect_mask_dtype_kernel(const unsigned char* __restrict__ m)
{
    // Scan first PP*NPOLY bytes (= whole buffer if uint8, first 1/4 if int32).
    // If dtype is int32 with values 0/1, every byte at offset %4!=0 is 0.
    // If dtype is uint8 with random 0/1 flags, many of those bytes are 1.
    __shared__ int found;
    if (threadIdx.x == 0) found = 0;
    __syncthreads();
    int local = 0;
    for (int i = threadIdx.x; i < NPOLY * PP; i += blockDim.x) {
        if ((i & 3) != 0 && m[i] != 0) local = 1;
    }
    if (local) atomicOr(&found, 1);
    __syncthreads();
    if (threadIdx.x == 0) g_mask_is_byte = found;
}

__device__ __forceinline__ ull pack2(float x) {
    ull r; unsigned u = __float_as_uint(x);
    asm("mov.b64 %0, {%1, %1};" : "=l"(r) : "r"(u));
    return r;
}

__device__ __forceinline__ void ffma2(ull& d, ull a, ull b) {
    // packed fp32x2 FMA (sm_100+): d = a*b + d, lanewise on two packed f32
    asm("fma.rn.f32x2 %0, %1, %2, %0;" : "+l"(d) : "l"(a), "l"(b));
}

__device__ __forceinline__ float2 unpack2(ull v) {
    unsigned lo, hi;
    asm("mov.b64 {%0, %1}, %2;" : "=r"(lo), "=r"(hi) : "l"(v));
    float2 f; f.x = __uint_as_float(lo); f.y = __uint_as_float(hi);
    return f;
}

// dst[p][e] = sum_d src[p][d] * Wg[d*128+e] + addvec[e]
__device__ __forceinline__ void gemm_64x128x128(
    const float* __restrict__ Wg, const float* src, float* dst,
    const float* addvec, int tid)
{
    const int eg = tid & 15;      // 16 e-groups of 8 outputs
    const int pg = tid >> 4;      // 16 point-groups of 4 points
    const int e0 = eg * 8;
    const int p0 = pg * 4;

    ull acc[4][4];
    #pragma unroll
    for (int j = 0; j < 4; ++j)
        #pragma unroll
        for (int i = 0; i < 4; ++i) acc[j][i] = 0ull;

    const float* wp = Wg + e0;
    const float* s0 = src + p0 * LROWS;

    #pragma unroll 4
    for (int d = 0; d < DD; ++d) {
        ulonglong2 wa = *(const ulonglong2*)(wp + (size_t)d * DD);
        ulonglong2 wb = *(const ulonglong2*)(wp + (size_t)d * DD + 4);
        ull hh[4];
        #pragma unroll
        for (int j = 0; j < 4; ++j) hh[j] = pack2(s0[j * LROWS + d]);
        #pragma unroll
        for (int j = 0; j < 4; ++j) {
            ffma2(acc[j][0], wa.x, hh[j]);
            ffma2(acc[j][1], wa.y, hh[j]);
            ffma2(acc[j][2], wb.x, hh[j]);
            ffma2(acc[j][3], wb.y, hh[j]);
        }
    }

    float av[8];
    #pragma unroll
    for (int i = 0; i < 8; ++i) av[i] = addvec[e0 + i];

    #pragma unroll
    for (int j = 0; j < 4; ++j) {
        float* drow = dst + (p0 + j) * LROWS + e0;
        #pragma unroll
        for (int i = 0; i < 4; ++i) {
            float2 v = unpack2(acc[j][i]);
            v.x += av[2 * i];
            v.y += av[2 * i + 1];
            *(float2*)(drow + 2 * i) = v;
        }
    }
}

__global__ void __launch_bounds__(256)
pointnet_fused_kernel(
    const float* __restrict__ x,            // (2048, 64, 128)
    const void* __restrict__ maskv,         // (2048, 64) : nonzero == valid point
    const float* __restrict__ W1,           // (3, 128, 128)
    const float* __restrict__ b1,           // (3, 128)
    const float* __restrict__ ln_g,         // (3, 128)
    const float* __restrict__ ln_b,         // (3, 128)
    const float* __restrict__ W2,           // (3, 256, 128)
    const float* __restrict__ b2,           // (3, 128)
    float* __restrict__ out)                // (2048, 128)
{
    extern __shared__ float smem[];
    float* h   = smem;
    float* h2  = smem + PP * LROWS;
    float* agg = smem + 2 * PP * LROWS;
    float* agp = agg + 128;
    int*  valid = (int*)(agp + 128);

    const int poly = blockIdx.x;
    const int tid  = threadIdx.x;

    // ---- mask / early exit for fully-invalid polygons ----
    int pred = 0;
    if (tid < PP) {
        if (g_mask_is_byte) {
            pred = (((const unsigned char*)maskv)[(size_t)poly * PP + tid] != 0) ? 1 : 0;
        } else {
            pred = (((const int*)maskv)[(size_t)poly * PP + tid] != 0) ? 1 : 0;
        }
        valid[tid] = pred;
    }
    int anyv = __syncthreads_or(pred);
    if (!anyv) {
        if (tid < DD) out[(size_t)poly * DD + tid] = 0.0f;
        return;
    }

    // ---- load x tile into SMEM (coalesced float4) ----
    {
        const float4* xv = (const float4*)(x + (size_t)poly * PP * DD);
        for (int i = tid; i < PP * DD / 4; i += 256) {
            int p = i >> 5;        // 32 float4 per row
            int c = i & 31;
            *(float4*)&h[p * LROWS + c * 4] = xv[i];
        }
    }
    __syncthreads();

    const int lp = tid >> 2;   // LN: 4 threads per point
    const int lq = tid & 3;

    for (int l = 0; l < NLAYER; ++l) {
        const float* W1l = W1 + (size_t)l * DD * DD;
        const float* b1l = b1 + l * DD;
        const float* gl  = ln_g + l * DD;
        const float* bl  = ln_b + l * DD;
        const float* W2l = W2 + (size_t)l * 2 * DD * DD;
        const float* b2l = b2 + l * DD;

        // GEMM1: h2 = h @ W1l + b1l
        gemm_64x128x128(W1l, h, h2, b1l, tid);
        __syncthreads();

        // LayerNorm + ReLU in place on h2 (4 threads per point row)
        {
            float* row = h2 + lp * LROWS + lq * 32;
            float s = 0.f, s2 = 0.f;
            #pragma unroll 8
            for (int j = 0; j < 32; ++j) {
                float v = row[j];
                s += v; s2 += v * v;
            }
            s  += __shfl_xor_sync(0xffffffffu, s, 1);
            s  += __shfl_xor_sync(0xffffffffu, s, 2);
            s2 += __shfl_xor_sync(0xffffffffu, s2, 1);
            s2 += __shfl_xor_sync(0xffffffffu, s2, 2);
            float mean = s * (1.0f / DD);
            float var  = s2 * (1.0f / DD) - mean * mean;
            float rs = rsqrtf(var + LN_EPS);
            #pragma unroll 8
            for (int j = 0; j < 32; ++j) {
                int e = lq * 32 + j;
                float v = (row[j] - mean) * rs * gl[e] + bl[e];
                row[j] = fmaxf(v, 0.0f);
            }
        }
        __syncthreads();

        // masked max over points -> agg[e]
        if (tid < DD) {
            float m = -INFINITY;
            for (int p = 0; p < PP; ++p)
                if (valid[p]) m = fmaxf(m, h2[p * LROWS + tid]);
            agg[tid] = m;
        }
        __syncthreads();

        // rank-1 part of concat GEMM: agp[e] = b2[e] + sum_f agg[f]*W2l[128+f][e]
        if (tid < DD) {
            float ap = b2l[tid];
            const float* w2a = W2l + (size_t)DD * DD + tid;
            #pragma unroll 8
            for (int f = 0; f < DD; ++f)
                ap = fmaf(agg[f], w2a[(size_t)f * DD], ap);
            agp[tid] = ap;
        }
        __syncthreads();

        // GEMM2: h = h2 @ W2l[0:128] + agp
        gemm_64x128x128(W2l, h2, h, agp, tid);
        __syncthreads();
    }

    // final masked max over points
    if (tid < DD) {
        float m = -INFINITY;
        for (int p = 0; p < PP; ++p)
            if (valid[p]) m = fmaxf(m, h[p * LROWS + tid]);
        out[(size_t)poly * DD + tid] = m;
    }
}

extern "C" void kernel_launch(void* const* d_in, const int* in_sizes, int n_in,
                              void* d_out, int out_size)
{
    const float*         x    = (const float*)d_in[0];
    const void*          mask = d_in[1];
    const float*         W1   = (const float*)d_in[2];
    const float*         b1   = (const float*)d_in[3];
    const float*         ln_g = (const float*)d_in[4];
    const float*         ln_b = (const float*)d_in[5];
    const float*         W2   = (const float*)d_in[6];
    const float*         b2   = (const float*)d_in[7];
    float* out = (float*)d_out;

    detect_mask_dtype_kernel<<<1, 256>>>((const unsigned char*)mask);

    cudaFuncSetAttribute(pointnet_fused_kernel,
                         cudaFuncAttributeMaxDynamicSharedMemorySize, SMEM_BYTES);
    pointnet_fused_kernel<<<NPOLY, 256, SMEM_BYTES>>>(
        x, mask, W1, b1, ln_g, ln_b, W2, b2, out);
}

// round 3
// speedup vs baseline: 1.5664x; 1.5664x over previous
#include <cuda_runtime.h>
#include <math.h>
#include <stdint.h>

// Problem constants
#define NPOLY 2048      // B*N
#define PP    64        // points per polygon
#define DD    128       // feature dim
#define NLAYER 3
#define LROWS 132       // activation row stride (floats), 2 polys => 128 rows
#define WSTR  132       // staged-weight row stride
#define KC    32        // K-chunk rows staged per buffer
#define LN_EPS 1e-5f

// SMEM: h[128*132] h2[128*132] Ws[2*32*132] agg[2*128] agp[2*128] valid[128] anyv[2]+pad
#define SMEM_FLOATS (2*128*LROWS + 2*KC*WSTR + 256 + 256 + 132)
#define SMEM_BYTES  (SMEM_FLOATS * 4)

typedef unsigned long long ull;

// 0 = int32 mask elements, 1 = byte mask elements
__device__ int g_mask_is_byte;

__global__ void detect_mask_dtype_kernel(const unsigned char* __restrict__ m)
{
    __shared__ int found;
    if (threadIdx.x == 0) found = 0;
    __syncthreads();
    int local = 0;
    for (int i = threadIdx.x; i < NPOLY * PP; i += blockDim.x)
        if ((i & 3) != 0 && m[i] != 0) local = 1;
    if (local) atomicOr(&found, 1);
    __syncthreads();
    if (threadIdx.x == 0) g_mask_is_byte = found;
}

__device__ __forceinline__ ull pack2(float x) {
    ull r; unsigned u = __float_as_uint(x);
    asm("mov.b64 %0, {%1, %1};" : "=l"(r) : "r"(u));
    return r;
}
__device__ __forceinline__ void ffma2(ull& d, ull a, ull b) {
    asm("fma.rn.f32x2 %0, %1, %2, %0;" : "+l"(d) : "l"(a), "l"(b));
}
__device__ __forceinline__ float2 unpack2(ull v) {
    unsigned lo, hi;
    asm("mov.b64 {%0, %1}, %2;" : "=r"(lo), "=r"(hi) : "l"(v));
    float2 f; f.x = __uint_as_float(lo); f.y = __uint_as_float(hi);
    return f;
}

// dst[p][e] = sum_d src[p][d]*Wg[d*128+e] + add[e]
// p in [0,128) covering 2 polygons. Weights staged through SMEM double buffer Ws.
// If biasG != nullptr: add = biasG[e] (global, shared by both polys).
// Else: add = agpS[(p>=64)*128 + e] (smem, per-poly).
__device__ __forceinline__ void gemm2poly(
    const float* __restrict__ Wg, const float* src, float* dst,
    const float* agpS, const float* __restrict__ biasG,
    float* Ws, int tid)
{
    const int e_tid = tid & 15;
    const int p_tid = tid >> 4;
    const int e0 = e_tid * 8;
    const int p0 = p_tid * 8;

    ull acc[8][4];
    #pragma unroll
    for (int j = 0; j < 8; ++j)
        #pragma unroll
        for (int i = 0; i < 4; ++i) acc[j][i] = 0ull;

    // preload chunk 0
    float4 pre[4];
    #pragma unroll
    for (int k = 0; k < 4; ++k) {
        int i = tid + k * 256; int r = i >> 5, c2 = i & 31;
        pre[k] = __ldg((const float4*)&Wg[r * DD + c2 * 4]);
    }
    #pragma unroll
    for (int k = 0; k < 4; ++k) {
        int i = tid + k * 256; int r = i >> 5, c2 = i & 31;
        *(float4*)&Ws[r * WSTR + c2 * 4] = pre[k];
    }
    __syncthreads();

    #pragma unroll 1
    for (int c = 0; c < 4; ++c) {
        if (c < 3) {
            #pragma unroll
            for (int k = 0; k < 4; ++k) {
                int i = tid + k * 256; int r = i >> 5, c2 = i & 31;
                pre[k] = __ldg((const float4*)&Wg[((c + 1) * KC + r) * DD + c2 * 4]);
            }
        }
        const float* Wb = Ws + (c & 1) * (KC * WSTR);
        const float* srcb = src + p0 * LROWS + c * KC;
        #pragma unroll 4
        for (int dd = 0; dd < KC; ++dd) {
            const float* wrow = Wb + dd * WSTR + e0;
            ulonglong2 wa = *(const ulonglong2*)wrow;
            ulonglong2 wb = *(const ulonglong2*)(wrow + 4);
            #pragma unroll
            for (int j = 0; j < 8; ++j) {
                ull hh = pack2(srcb[j * LROWS + dd]);
                ffma2(acc[j][0], wa.x, hh);
                ffma2(acc[j][1], wa.y, hh);
                ffma2(acc[j][2], wb.x, hh);
                ffma2(acc[j][3], wb.y, hh);
            }
        }
        __syncthreads();
        if (c < 3) {
            #pragma unroll
            for (int k = 0; k < 4; ++k) {
                int i = tid + k * 256; int r = i >> 5, c2 = i & 31;
                *(float4*)&Ws[((c + 1) & 1) * (KC * WSTR) + r * WSTR + c2 * 4] = pre[k];
            }
            __syncthreads();
        }
    }

    // epilogue: add vector, write dst
    float av[8];
    if (biasG) {
        float4 bA = __ldg((const float4*)&biasG[e0]);
        float4 bB = __ldg((const float4*)&biasG[e0 + 4]);
        av[0]=bA.x; av[1]=bA.y; av[2]=bA.z; av[3]=bA.w;
        av[4]=bB.x; av[5]=bB.y; av[6]=bB.z; av[7]=bB.w;
    } else {
        const float* ap = agpS + ((p0 >= 64) ? 128 : 0) + e0;
        float4 bA = *(const float4*)ap;
        float4 bB = *(const float4*)(ap + 4);
        av[0]=bA.x; av[1]=bA.y; av[2]=bA.z; av[3]=bA.w;
        av[4]=bB.x; av[5]=bB.y; av[6]=bB.z; av[7]=bB.w;
    }
    #pragma unroll
    for (int j = 0; j < 8; ++j) {
        float2 v0 = unpack2(acc[j][0]);
        float2 v1 = unpack2(acc[j][1]);
        float2 v2 = unpack2(acc[j][2]);
        float2 v3 = unpack2(acc[j][3]);
        float4 o0 = {v0.x + av[0], v0.y + av[1], v1.x + av[2], v1.y + av[3]};
        float4 o1 = {v2.x + av[4], v2.y + av[5], v3.x + av[6], v3.y + av[7]};
        float* drow = dst + (p0 + j) * LROWS + e0;
        *(float4*)drow = o0;
        *(float4*)(drow + 4) = o1;
    }
}

__global__ void __launch_bounds__(256)
pointnet_fused_kernel(
    const float* __restrict__ x,            // (2048, 64, 128)
    const void* __restrict__ maskv,         // (2048, 64) nonzero == valid
    const float* __restrict__ W1,           // (3, 128, 128)
    const float* __restrict__ b1,           // (3, 128)
    const float* __restrict__ ln_g,         // (3, 128)
    const float* __restrict__ ln_b,         // (3, 128)
    const float* __restrict__ W2,           // (3, 256, 128)
    const float* __restrict__ b2,           // (3, 128)
    float* __restrict__ out)                // (2048, 128)
{
    extern __shared__ float smem[];
    float* h   = smem;                       // 128 x LROWS
    float* h2  = h + 128 * LROWS;            // 128 x LROWS
    float* Ws  = h2 + 128 * LROWS;           // 2 x KC x WSTR
    float* agg = Ws + 2 * KC * WSTR;         // 2 x 128
    float* agp = agg + 256;                  // 2 x 128
    int* valid = (int*)(agp + 256);          // 128
    int* anyv  = valid + 128;                // 2

    const int bx  = blockIdx.x;              // covers polys 2bx, 2bx+1
    const int tid = threadIdx.x;

    // ---- masks for both polys ----
    if (tid < 128) {
        int poly = bx * 2 + (tid >> 6);
        int p = tid & 63;
        int v;
        if (g_mask_is_byte)
            v = (((const unsigned char*)maskv)[(size_t)poly * PP + p] != 0);
        else
            v = (((const int*)maskv)[(size_t)poly * PP + p] != 0);
        valid[tid] = v;
    }
    __syncthreads();
    if (tid < 2) {
        int a = 0;
        for (int p = 0; p < 64; ++p) a |= valid[tid * 64 + p];
        anyv[tid] = a;
    }

    // ---- load x for both polys, coalesced float4 ----
    {
        const float4* xv = (const float4*)(x + (size_t)bx * 128 * DD);
        #pragma unroll
        for (int k = 0; k < 16; ++k) {
            int i = tid + k * 256;
            int p = i >> 5, c = i & 31;
            *(float4*)&h[p * LROWS + c * 4] = xv[i];
        }
    }
    __syncthreads();

    const int lane = tid & 31;
    const int wid  = tid >> 5;

    for (int l = 0; l < NLAYER; ++l) {
        const float* W1l = W1 + (size_t)l * DD * DD;
        const float* b1l = b1 + l * DD;
        const float* gl  = ln_g + l * DD;
        const float* bl  = ln_b + l * DD;
        const float* W2l = W2 + (size_t)l * 2 * DD * DD;
        const float* b2l = b2 + l * DD;

        // GEMM1: h2 = h @ W1l + b1l
        gemm2poly(W1l, h, h2, nullptr, b1l, Ws, tid);
        __syncthreads();

        // LayerNorm + ReLU in place on h2 (2 threads per point, vectorized)
        {
            int pt = tid >> 1, lq = tid & 1;
            float* row = h2 + pt * LROWS + lq * 64;
            float s = 0.f, s2 = 0.f;
            #pragma unroll
            for (int j = 0; j < 16; ++j) {
                float4 v = *(float4*)&row[j * 4];
                s  += v.x + v.y + v.z + v.w;
                s2 += v.x*v.x + v.y*v.y + v.z*v.z + v.w*v.w;
            }
            s  += __shfl_xor_sync(0xffffffffu, s, 1);
            s2 += __shfl_xor_sync(0xffffffffu, s2, 1);
            float mean = s * (1.0f / DD);
            float var  = s2 * (1.0f / DD) - mean * mean;
            float rs = rsqrtf(var + LN_EPS);
            #pragma unroll
            for (int j = 0; j < 16; ++j) {
                float4 v = *(float4*)&row[j * 4];
                float4 g4 = __ldg((const float4*)&gl[lq * 64 + j * 4]);
                float4 b4 = __ldg((const float4*)&bl[lq * 64 + j * 4]);
                v.x = fmaxf((v.x - mean) * rs * g4.x + b4.x, 0.f);
                v.y = fmaxf((v.y - mean) * rs * g4.y + b4.y, 0.f);
                v.z = fmaxf((v.z - mean) * rs * g4.z + b4.z, 0.f);
                v.w = fmaxf((v.w - mean) * rs * g4.w + b4.w, 0.f);
                *(float4*)&row[j * 4] = v;
            }
        }
        __syncthreads();

        // masked max over points per poly -> agg; init agp with b2
        {
            int e = tid & 127, s = tid >> 7;
            float m = -INFINITY;
            const float* col = h2 + s * 64 * LROWS + e;
            const int* vb = valid + s * 64;
            for (int p = 0; p < 64; ++p) {
                float v = col[p * LROWS];
                m = vb[p] ? fmaxf(m, v) : m;
            }
            agg[s * 128 + e] = m;
            agp[s * 128 + e] = __ldg(&b2l[e]);
        }
        __syncthreads();

        // rank-1 term: agp[s][e] += sum_f agg[s][f] * W2l[128+f][e]
        {
            int s = wid >> 2;            // warps 0-3 poly0, 4-7 poly1
            int f0 = (wid & 3) * 32;
            const float* W2b = W2l + (size_t)DD * DD;
            float4 a4 = {0.f, 0.f, 0.f, 0.f};
            for (int f = f0; f < f0 + 32; ++f) {
                float av = agg[s * 128 + f];
                float4 wv = __ldg((const float4*)&W2b[(size_t)f * DD + lane * 4]);
                a4.x = fmaf(av, wv.x, a4.x);
                a4.y = fmaf(av, wv.y, a4.y);
                a4.z = fmaf(av, wv.z, a4.z);
                a4.w = fmaf(av, wv.w, a4.w);
            }
            float* ap = agp + s * 128 + lane * 4;
            atomicAdd(ap + 0, a4.x);
            atomicAdd(ap + 1, a4.y);
            atomicAdd(ap + 2, a4.z);
            atomicAdd(ap + 3, a4.w);
        }
        // gemm2poly's first internal __syncthreads orders the atomics
        // before any thread reads agp (read only in its epilogue).

        // GEMM2: h = h2 @ W2l[0:128] + agp
        gemm2poly(W2l, h2, h, agp, nullptr, Ws, tid);
        __syncthreads();
    }

    // final masked max per poly
    {
        int e = tid & 127, s = tid >> 7;
        float m = -INFINITY;
        const float* col = h + s * 64 * LROWS + e;
        const int* vb = valid + s * 64;
        for (int p = 0; p < 64; ++p) {
            float v = col[p * LROWS];
            m = vb[p] ? fmaxf(m, v) : m;
        }
        int poly = bx * 2 + s;
        out[(size_t)poly * DD + e] = anyv[s] ? m : 0.0f;
    }
}

extern "C" void kernel_launch(void* const* d_in, const int* in_sizes, int n_in,
                              void* d_out, int out_size)
{
    const float* x    = (const float*)d_in[0];
    const void*  mask = d_in[1];
    const float* W1   = (const float*)d_in[2];
    const float* b1   = (const float*)d_in[3];
    const float* ln_g = (const float*)d_in[4];
    const float* ln_b = (const float*)d_in[5];
    const float* W2   = (const float*)d_in[6];
    const float* b2   = (const float*)d_in[7];
    float* out = (float*)d_out;

    detect_mask_dtype_kernel<<<1, 256>>>((const unsigned char*)mask);

    cudaFuncSetAttribute(pointnet_fused_kernel,
                         cudaFuncAttributeMaxDynamicSharedMemorySize, SMEM_BYTES);
    pointnet_fused_kernel<<<NPOLY / 2, 256, SMEM_BYTES>>>(
        x, mask, W1, b1, ln_g, ln_b, W2, b2, out);
}